// round 16
// baseline (speedup 1.0000x reference)
#include <cuda_runtime.h>
#include <cuda_fp16.h>
#include <math.h>
#include <stdint.h>

#define B_DIM 4096
#define IN_DIM 512
#define H_DIM 1024
#define NGATE (4 * H_DIM)          // 4096
#define KTOT  (IN_DIM + H_DIM)     // 1536
#define KC 32                      // K per stage (fp16)
#define NSTAGE (KTOT / KC)         // 48

// fp16 hi/lo split copies of A = [input | hx] and B = permuted [Wxh | Whh]
__device__ __align__(16) __half g_Ah[(size_t)B_DIM * KTOT];
__device__ __align__(16) __half g_Al[(size_t)B_DIM * KTOT];
__device__ __align__(16) __half g_Bh[(size_t)NGATE * KTOT];
__device__ __align__(16) __half g_Bl[(size_t)NGATE * KTOT];

// ---------------- asm helpers (sm_80-compatible PTX only) ----------------

__device__ __forceinline__ uint32_t smem_u32(const void* p) {
    uint32_t a;
    asm("{ .reg .u64 t; cvta.to.shared.u64 t, %1; cvt.u32.u64 %0, t; }"
        : "=r"(a) : "l"(p));
    return a;
}

__device__ __forceinline__ void cpasync16(uint32_t dst, const void* src) {
    asm volatile("cp.async.cg.shared.global [%0], [%1], 16;"
                 :: "r"(dst), "l"(__cvta_generic_to_global(src)) : "memory");
}
#define CP_COMMIT() asm volatile("cp.async.commit_group;" ::: "memory")
#define CP_WAIT(n)  asm volatile("cp.async.wait_group %0;" :: "n"(n) : "memory")

__device__ __forceinline__ void ldsm_x4(uint32_t& r0, uint32_t& r1,
                                        uint32_t& r2, uint32_t& r3, uint32_t a) {
    asm volatile("ldmatrix.sync.aligned.m8n8.x4.shared.b16 {%0,%1,%2,%3}, [%4];"
                 : "=r"(r0), "=r"(r1), "=r"(r2), "=r"(r3) : "r"(a));
}

__device__ __forceinline__ void mma_f16(float* d, const uint32_t* a,
                                        const uint32_t* b) {
    asm volatile(
        "mma.sync.aligned.m16n8k16.row.col.f32.f16.f16.f32 "
        "{%0,%1,%2,%3}, {%4,%5,%6,%7}, {%8,%9}, {%0,%1,%2,%3};"
        : "+f"(d[0]), "+f"(d[1]), "+f"(d[2]), "+f"(d[3])
        : "r"(a[0]), "r"(a[1]), "r"(a[2]), "r"(a[3]), "r"(b[0]), "r"(b[1]));
}

__device__ __forceinline__ float sigf(float x) { return 1.0f / (1.0f + expf(-x)); }

// ---------------- fused prep kernel ----------------

struct alignas(16) Hf8 { __half h[8]; };

__device__ __forceinline__ void split8(const float* f, Hf8& hi, Hf8& lo) {
#pragma unroll
    for (int e = 0; e < 8; e++) {
        __half h = __float2half_rn(f[e]);
        hi.h[e] = h;
        lo.h[e] = __float2half_rn(f[e] - __half2float(h));
    }
}

// blocks [0,3072): A rows; blocks [3072,6144): B rows (permuted)
__global__ __launch_bounds__(256) void prep_kernel(
    const float* __restrict__ input, const float* __restrict__ hx,
    const float* __restrict__ Wxh, const float* __restrict__ Whh)
{
    int bid = blockIdx.x;
    if (bid < 3072) {
        int idx = bid * 256 + threadIdx.x;
        int row = idx / 192;
        int k = (idx % 192) * 8;
        const float* src = (k < IN_DIM) ? (input + (size_t)row * IN_DIM + k)
                                        : (hx + (size_t)row * H_DIM + (k - IN_DIM));
        float f[8];
        float4 v0 = ((const float4*)src)[0];
        float4 v1 = ((const float4*)src)[1];
        f[0]=v0.x; f[1]=v0.y; f[2]=v0.z; f[3]=v0.w;
        f[4]=v1.x; f[5]=v1.y; f[6]=v1.z; f[7]=v1.w;
        Hf8 hi, lo; split8(f, hi, lo);
        *(uint4*)&g_Ah[(size_t)row * KTOT + k] = *(const uint4*)&hi;
        *(uint4*)&g_Al[(size_t)row * KTOT + k] = *(const uint4*)&lo;
    } else {
        int idx = (bid - 3072) * 256 + threadIdx.x;
        int rowp = idx / 192;                 // row' = (h>>3)*32 + g*8 + (h&7)
        int k = (idx % 192) * 8;
        int g = (rowp >> 3) & 3;
        int h = ((rowp >> 5) << 3) | (rowp & 7);
        int orig = g * H_DIM + h;
        const float* src = (k < IN_DIM) ? (Wxh + (size_t)orig * IN_DIM + k)
                                        : (Whh + (size_t)orig * H_DIM + (k - IN_DIM));
        float f[8];
        float4 v0 = ((const float4*)src)[0];
        float4 v1 = ((const float4*)src)[1];
        f[0]=v0.x; f[1]=v0.y; f[2]=v0.z; f[3]=v0.w;
        f[4]=v1.x; f[5]=v1.y; f[6]=v1.z; f[7]=v1.w;
        Hf8 hi, lo; split8(f, hi, lo);
        *(uint4*)&g_Bh[(size_t)rowp * KTOT + k] = *(const uint4*)&hi;
        *(uint4*)&g_Bl[(size_t)rowp * KTOT + k] = *(const uint4*)&lo;
    }
}

// ---------------- fused HMMA GEMM + phased-LSTM epilogue ----------------
// CTA tile 128(M) x 64(N), 16 warps (warp tile 16x32), ring-2, 2 CTAs/SM
// => 32 warps/SM = 8 warps per SMSP (the untested occupancy point).

#define ROW_B 80                       // 64B data + 16B pad (conflict-free)
#define ATILE (128 * ROW_B)            // 10240
#define BTILE (64 * ROW_B)             // 5120
#define STAGE_SZ (2 * ATILE + 2 * BTILE)   // 30720
#define NRING 2
#define SMEM_BYTES (NRING * STAGE_SZ)  // 61440  (x2 CTAs = 122880)

__global__ __launch_bounds__(512, 2) void gemm_fused_kernel(
    const float* __restrict__ time_,  // [B]
    const float* __restrict__ cx,     // [B, H]
    const float* __restrict__ tau,
    const float* __restrict__ s,
    const float* __restrict__ alpha_p,
    const float* __restrict__ rho_p,
    const float* __restrict__ bias,   // [4H]
    float* __restrict__ out)          // hy then cy
{
    extern __shared__ char smem[];
    const uint32_t sb = smem_u32(smem);
    const int tid = threadIdx.x;
    const int wid = tid >> 5;          // 0..15
    const int lane = tid & 31;
    const int wm = wid >> 1;           // 0..7  warp M base = wm*16
    const int wn = wid & 1;            // 0..1  warp N base = wn*32

    const int m0 = blockIdx.y * 128;
    const int n0 = blockIdx.x * 64;

    // --- global-load mapping (512 threads) ---
    // A halves: 128 rows x 4 uint4 = 512 -> one per thread.
    // B halves: 64 rows x 4 uint4 = 256 -> threads [0,256) do Bh, [256,512) Bl.
    const int a_row = tid >> 2;         // 0..127
    const int a_c4  = tid & 3;          // 0..3
    const uint32_t stA_off = (uint32_t)a_row * ROW_B + a_c4 * 16;
    const int b_row = (tid & 255) >> 2; // 0..63
    const uint32_t stB_off = (uint32_t)b_row * ROW_B + a_c4 * 16;
    const int g_kelem = a_c4 * 8;

    const __half* pAh = g_Ah + (size_t)(m0 + a_row) * KTOT + g_kelem;
    const __half* pAl = g_Al + (size_t)(m0 + a_row) * KTOT + g_kelem;
    const __half* pB  = (tid < 256)
        ? (g_Bh + (size_t)(n0 + b_row) * KTOT + g_kelem)
        : (g_Bl + (size_t)(n0 + b_row) * KTOT + g_kelem);
    const uint32_t bTileOff = (tid < 256) ? (2u * ATILE) : (2u * ATILE + BTILE);

    // --- ldmatrix lane offsets ---
    const int l15 = lane & 15;
    const uint32_t a_off =
        (uint32_t)(wm * 16 + l15) * ROW_B + (lane >> 4) * 16;
    uint32_t b_off[2];
    {
        int l7 = lane & 7;
        int rhalf = (lane >> 4) & 1;
        int chalf = (lane >> 3) & 1;
#pragma unroll
        for (int j = 0; j < 2; j++)
            b_off[j] = (uint32_t)(wn * 32 + j * 16 + rhalf * 8 + l7) * ROW_B + chalf * 16;
    }

    float acc[4][4];
#pragma unroll
    for (int nb = 0; nb < 4; nb++)
#pragma unroll
        for (int e = 0; e < 4; e++) acc[nb][e] = 0.0f;

#define ISSUE_STAGE(C, BUF) do {                                            \
    uint32_t base_ = sb + (uint32_t)(BUF) * STAGE_SZ;                       \
    size_t ke_ = (size_t)(C) * KC;                                          \
    cpasync16(base_ + stA_off,           pAh + ke_);                        \
    cpasync16(base_ + ATILE + stA_off,   pAl + ke_);                        \
    cpasync16(base_ + bTileOff + stB_off, pB + ke_);                        \
    CP_COMMIT();                                                            \
} while (0)

    ISSUE_STAGE(0, 0);
    ISSUE_STAGE(1, 1);

    for (int c = 0; c < NSTAGE; c++) {
        const int buf = c & 1;

        // Pending groups at top of iter c: {c, c+1}; require stage c done.
        if (c + 1 < NSTAGE) { CP_WAIT(1); }
        else                { CP_WAIT(0); }
        __syncthreads();                 // stage c data visible to all warps

        const uint32_t ahb = sb + (uint32_t)buf * STAGE_SZ;
        const uint32_t alb = ahb + ATILE;
        const uint32_t bhb = ahb + 2 * ATILE;
        const uint32_t blb = bhb + BTILE;

#pragma unroll
        for (int ks = 0; ks < 2; ks++) {
            const uint32_t ko = ks * 32;
            uint32_t ah[4], bh[4][2];
#pragma unroll
            for (int j = 0; j < 2; j++)
                ldsm_x4(bh[2*j][0], bh[2*j][1], bh[2*j+1][0], bh[2*j+1][1],
                        bhb + b_off[j] + ko);
            ldsm_x4(ah[0], ah[1], ah[2], ah[3], ahb + a_off + ko);
#pragma unroll
            for (int nb = 0; nb < 4; nb++)
                mma_f16(acc[nb], ah, bh[nb]);

            uint32_t bl[4][2];
#pragma unroll
            for (int j = 0; j < 2; j++)
                ldsm_x4(bl[2*j][0], bl[2*j][1], bl[2*j+1][0], bl[2*j+1][1],
                        blb + b_off[j] + ko);
#pragma unroll
            for (int nb = 0; nb < 4; nb++)
                mma_f16(acc[nb], ah, bl[nb]);

            uint32_t al[4];
            ldsm_x4(al[0], al[1], al[2], al[3], alb + a_off + ko);
#pragma unroll
            for (int nb = 0; nb < 4; nb++)
                mma_f16(acc[nb], al, bh[nb]);
        }

        // All warps done reading buf; safe to overwrite with stage c+2.
        __syncthreads();
        if (c + 2 < NSTAGE)
            ISSUE_STAGE(c + 2, buf);
    }

    // ---- fused epilogue ----
    // acc[nb][e]: m-row = m0 + wm*16 + (lane>>2) + (e>>1)*8
    //             gate = nb, h = (n0 + wn*32)/4 + 2*(lane&3) + (e&1)
    const int t = lane & 3;
    const int grow = lane >> 2;
    const int hb = ((n0 + wn * 32) >> 2) + 2 * t;

    const float alpha = alpha_p[0];
    const float rho = rho_p[0];
    const float inv_rho = 2.0f / rho;
    const float tu[2] = {tau[hb], tau[hb + 1]};
    const float sh[2] = {s[hb], s[hb + 1]};
    float bi[4][2];
#pragma unroll
    for (int g = 0; g < 4; g++) {
        bi[g][0] = bias[g * H_DIM + hb];
        bi[g][1] = bias[g * H_DIM + hb + 1];
    }

#pragma unroll
    for (int rsel = 0; rsel < 2; rsel++) {
        const int r = m0 + wm * 16 + grow + rsel * 8;
        const float tt = time_[r];
        const float2 cx2 = *(const float2*)&cx[(size_t)r * H_DIM + hb];
        const float cxa[2] = {cx2.x, cx2.y};
        float hy2[2], cy2[2];
#pragma unroll
        for (int e = 0; e < 2; e++) {
            const int d = rsel * 2 + e;
            float gi = acc[0][d] + bi[0][e];
            float gf = acc[1][d] + bi[1][e];
            float gg = acc[2][d] + bi[2][e];
            float go = acc[3][d] + bi[3][e];
            float phi = fmodf(tt - sh[e], tu[e]) / tu[e];
            float kg;
            if (phi < 0.5f * rho)      kg = phi * inv_rho;
            else if (phi < rho)        kg = 2.0f - phi * inv_rho;
            else                       kg = alpha * phi;
            float ft = sigf(gf + 1.0f - kg);
            float it = sigf(gi) * kg;
            float gt = tanhf(gg) * kg;
            float ot = sigf(go) * kg;
            float cyv = ft * cxa[e] + it * gt;
            cy2[e] = cyv;
            hy2[e] = ot * tanhf(cyv);
        }
        *(float2*)&out[(size_t)r * H_DIM + hb] = make_float2(hy2[0], hy2[1]);
        *(float2*)&out[(size_t)B_DIM * H_DIM + (size_t)r * H_DIM + hb] =
            make_float2(cy2[0], cy2[1]);
    }
}

// ---------------- launch ----------------

extern "C" void kernel_launch(void* const* d_in, const int* in_sizes, int n_in,
                              void* d_out, int out_size) {
    const float* input = (const float*)d_in[0];
    const float* time_ = (const float*)d_in[1];
    const float* hx    = (const float*)d_in[2];
    const float* cx    = (const float*)d_in[3];
    const float* Wxh_w = (const float*)d_in[4];
    const float* Wxh_b = (const float*)d_in[5];
    const float* Whh_w = (const float*)d_in[6];
    const float* tau   = (const float*)d_in[7];
    const float* s     = (const float*)d_in[8];
    const float* alpha = (const float*)d_in[9];
    const float* rho   = (const float*)d_in[10];
    float* out = (float*)d_out;

    cudaFuncSetAttribute(gemm_fused_kernel,
                         cudaFuncAttributeMaxDynamicSharedMemorySize, SMEM_BYTES);

    prep_kernel<<<6144, 256>>>(input, hx, Wxh_w, Whh_w);

    dim3 grid(NGATE / 64, B_DIM / 128);   // 64 x 32
    gemm_fused_kernel<<<grid, 512, SMEM_BYTES>>>(
        time_, cx, tau, s, alpha, rho, Wxh_b, out);
}

// round 17
// speedup vs baseline: 1.1358x; 1.1358x over previous
#include <cuda_runtime.h>
#include <cuda_fp16.h>
#include <math.h>
#include <stdint.h>

#define B_DIM 4096
#define IN_DIM 512
#define H_DIM 1024
#define NGATE (4 * H_DIM)          // 4096
#define KTOT  (IN_DIM + H_DIM)     // 1536
#define KC 32                      // K per stage (fp16)
#define NSTAGE (KTOT / KC)         // 48

#define N_TILES 2048               // 32 M-tiles x 64 N-tiles
#define GRID_CTAS 444              // 148 SMs x 3 CTAs/SM (fully resident)

// fp16 hi/lo split copies of A = [input | hx] and B = permuted [Wxh | Whh]
__device__ __align__(16) __half g_Ah[(size_t)B_DIM * KTOT];
__device__ __align__(16) __half g_Al[(size_t)B_DIM * KTOT];
__device__ __align__(16) __half g_Bh[(size_t)NGATE * KTOT];
__device__ __align__(16) __half g_Bl[(size_t)NGATE * KTOT];

__device__ unsigned int g_tile_ctr;

// ---------------- asm helpers (sm_80-compatible PTX only) ----------------

__device__ __forceinline__ uint32_t smem_u32(const void* p) {
    uint32_t a;
    asm("{ .reg .u64 t; cvta.to.shared.u64 t, %1; cvt.u32.u64 %0, t; }"
        : "=r"(a) : "l"(p));
    return a;
}

__device__ __forceinline__ void cpasync16(uint32_t dst, const void* src) {
    asm volatile("cp.async.cg.shared.global [%0], [%1], 16;"
                 :: "r"(dst), "l"(__cvta_generic_to_global(src)) : "memory");
}
#define CP_COMMIT() asm volatile("cp.async.commit_group;" ::: "memory")
#define CP_WAIT(n)  asm volatile("cp.async.wait_group %0;" :: "n"(n) : "memory")

__device__ __forceinline__ void ldsm_x4(uint32_t& r0, uint32_t& r1,
                                        uint32_t& r2, uint32_t& r3, uint32_t a) {
    asm volatile("ldmatrix.sync.aligned.m8n8.x4.shared.b16 {%0,%1,%2,%3}, [%4];"
                 : "=r"(r0), "=r"(r1), "=r"(r2), "=r"(r3) : "r"(a));
}

__device__ __forceinline__ void mma_f16(float* d, const uint32_t* a,
                                        const uint32_t* b) {
    asm volatile(
        "mma.sync.aligned.m16n8k16.row.col.f32.f16.f16.f32 "
        "{%0,%1,%2,%3}, {%4,%5,%6,%7}, {%8,%9}, {%0,%1,%2,%3};"
        : "+f"(d[0]), "+f"(d[1]), "+f"(d[2]), "+f"(d[3])
        : "r"(a[0]), "r"(a[1]), "r"(a[2]), "r"(a[3]), "r"(b[0]), "r"(b[1]));
}

__device__ __forceinline__ float sigf(float x) { return 1.0f / (1.0f + expf(-x)); }

// ---------------- fused prep kernel ----------------

struct alignas(16) Hf8 { __half h[8]; };

__device__ __forceinline__ void split8(const float* f, Hf8& hi, Hf8& lo) {
#pragma unroll
    for (int e = 0; e < 8; e++) {
        __half h = __float2half_rn(f[e]);
        hi.h[e] = h;
        lo.h[e] = __float2half_rn(f[e] - __half2float(h));
    }
}

// blocks [0,3072): A rows; blocks [3072,6144): B rows (permuted)
__global__ __launch_bounds__(256) void prep_kernel(
    const float* __restrict__ input, const float* __restrict__ hx,
    const float* __restrict__ Wxh, const float* __restrict__ Whh)
{
    int bid = blockIdx.x;
    if (bid < 3072) {
        int idx = bid * 256 + threadIdx.x;
        int row = idx / 192;
        int k = (idx % 192) * 8;
        const float* src = (k < IN_DIM) ? (input + (size_t)row * IN_DIM + k)
                                        : (hx + (size_t)row * H_DIM + (k - IN_DIM));
        float f[8];
        float4 v0 = ((const float4*)src)[0];
        float4 v1 = ((const float4*)src)[1];
        f[0]=v0.x; f[1]=v0.y; f[2]=v0.z; f[3]=v0.w;
        f[4]=v1.x; f[5]=v1.y; f[6]=v1.z; f[7]=v1.w;
        Hf8 hi, lo; split8(f, hi, lo);
        *(uint4*)&g_Ah[(size_t)row * KTOT + k] = *(const uint4*)&hi;
        *(uint4*)&g_Al[(size_t)row * KTOT + k] = *(const uint4*)&lo;
    } else {
        int idx = (bid - 3072) * 256 + threadIdx.x;
        int rowp = idx / 192;                 // row' = (h>>3)*32 + g*8 + (h&7)
        int k = (idx % 192) * 8;
        int g = (rowp >> 3) & 3;
        int h = ((rowp >> 5) << 3) | (rowp & 7);
        int orig = g * H_DIM + h;
        const float* src = (k < IN_DIM) ? (Wxh + (size_t)orig * IN_DIM + k)
                                        : (Whh + (size_t)orig * H_DIM + (k - IN_DIM));
        float f[8];
        float4 v0 = ((const float4*)src)[0];
        float4 v1 = ((const float4*)src)[1];
        f[0]=v0.x; f[1]=v0.y; f[2]=v0.z; f[3]=v0.w;
        f[4]=v1.x; f[5]=v1.y; f[6]=v1.z; f[7]=v1.w;
        Hf8 hi, lo; split8(f, hi, lo);
        *(uint4*)&g_Bh[(size_t)rowp * KTOT + k] = *(const uint4*)&hi;
        *(uint4*)&g_Bl[(size_t)rowp * KTOT + k] = *(const uint4*)&lo;
    }
}

__global__ void reset_ctr_kernel() { g_tile_ctr = 0; }

// ---------------- fused HMMA GEMM + phased-LSTM epilogue ----------------
// Persistent work-stealing: 444 CTAs (3/SM, 6 warps/SMSP) loop over 2048
// tiles via an atomic ticket. CTA tile 128(M) x 64(N), 8 warps (32x32),
// ring-2, KC=32 — the proven R15 schedule, minus the wave-tail.

#define ROW_B 80                       // 64B data + 16B pad (conflict-free)
#define ATILE (128 * ROW_B)            // 10240
#define BTILE (64 * ROW_B)             // 5120
#define STAGE_SZ (2 * ATILE + 2 * BTILE)   // 30720
#define NRING 2
#define SMEM_BYTES (NRING * STAGE_SZ)  // 61440  (x3 CTAs = 184320 <= 228K)

__global__ __launch_bounds__(256, 3) void gemm_fused_kernel(
    const float* __restrict__ time_,  // [B]
    const float* __restrict__ cx,     // [B, H]
    const float* __restrict__ tau,
    const float* __restrict__ s,
    const float* __restrict__ alpha_p,
    const float* __restrict__ rho_p,
    const float* __restrict__ bias,   // [4H]
    float* __restrict__ out)          // hy then cy
{
    extern __shared__ char smem[];
    __shared__ int s_tile;
    const uint32_t sb = smem_u32(smem);
    const int tid = threadIdx.x;
    const int wid = tid >> 5;
    const int lane = tid & 31;
    const int wm = wid >> 1;          // 0..3  warp M base = wm*32
    const int wn = wid & 1;           // 0..1  warp N base = wn*32

    // --- tid-only constants (tile-independent) ---
    const int g_row = tid >> 2;        // 0..63
    const int g_c4  = tid & 3;         // 0..3
    const uint32_t st_off   = (uint32_t)g_row * ROW_B + g_c4 * 16;
    const uint32_t st_off64 = st_off + 64 * ROW_B;
    const int g_kelem = g_c4 * 8;
    const size_t row64 = (size_t)64 * KTOT;

    const int l15 = lane & 15;
    uint32_t a_off[2];
#pragma unroll
    for (int i = 0; i < 2; i++)
        a_off[i] = (uint32_t)(wm * 32 + i * 16 + l15) * ROW_B + (lane >> 4) * 16;
    uint32_t b_off[2];
    {
        int l7 = lane & 7;
        int rhalf = (lane >> 4) & 1;
        int chalf = (lane >> 3) & 1;
#pragma unroll
        for (int j = 0; j < 2; j++)
            b_off[j] = (uint32_t)(wn * 32 + j * 16 + rhalf * 8 + l7) * ROW_B + chalf * 16;
    }

    const float alpha = alpha_p[0];
    const float rho = rho_p[0];
    const float inv_rho = 2.0f / rho;

    for (;;) {
        // Ticket + smem-reuse fence (all warps done with previous tile's smem).
        if (tid == 0) s_tile = (int)atomicAdd(&g_tile_ctr, 1u);
        __syncthreads();
        const int tile = s_tile;
        if (tile >= N_TILES) break;

        const int m0 = (tile >> 6) * 128;   // 32 M-tiles
        const int n0 = (tile & 63) * 64;    // 64 N-tiles (fastest -> L2 A reuse)

        const __half* pAh = g_Ah + (size_t)(m0 + g_row) * KTOT + g_kelem;
        const __half* pAl = g_Al + (size_t)(m0 + g_row) * KTOT + g_kelem;
        const __half* pBh = g_Bh + (size_t)(n0 + g_row) * KTOT + g_kelem;
        const __half* pBl = g_Bl + (size_t)(n0 + g_row) * KTOT + g_kelem;

        float acc[2][4][4];
#pragma unroll
        for (int i = 0; i < 2; i++)
#pragma unroll
            for (int nb = 0; nb < 4; nb++)
#pragma unroll
                for (int e = 0; e < 4; e++) acc[i][nb][e] = 0.0f;

#define ISSUE_STAGE(C, BUF) do {                                            \
    uint32_t base_ = sb + (uint32_t)(BUF) * STAGE_SZ;                       \
    size_t ke_ = (size_t)(C) * KC;                                          \
    cpasync16(base_ + st_off,                      pAh + ke_);              \
    cpasync16(base_ + st_off64,                    pAh + row64 + ke_);      \
    cpasync16(base_ + ATILE + st_off,              pAl + ke_);              \
    cpasync16(base_ + ATILE + st_off64,            pAl + row64 + ke_);      \
    cpasync16(base_ + 2*ATILE + st_off,            pBh + ke_);              \
    cpasync16(base_ + 2*ATILE + BTILE + st_off,    pBl + ke_);              \
    CP_COMMIT();                                                            \
} while (0)

        ISSUE_STAGE(0, 0);
        ISSUE_STAGE(1, 1);

        for (int c = 0; c < NSTAGE; c++) {
            const int buf = c & 1;

            if (c + 1 < NSTAGE) { CP_WAIT(1); }
            else                { CP_WAIT(0); }
            __syncthreads();             // stage c data visible to all warps

            const uint32_t ahb = sb + (uint32_t)buf * STAGE_SZ;
            const uint32_t alb = ahb + ATILE;
            const uint32_t bhb = ahb + 2 * ATILE;
            const uint32_t blb = bhb + BTILE;

#pragma unroll
            for (int ks = 0; ks < 2; ks++) {
                const uint32_t ko = ks * 32;
                uint32_t ah[2][4], bh[4][2];
#pragma unroll
                for (int j = 0; j < 2; j++)
                    ldsm_x4(bh[2*j][0], bh[2*j][1], bh[2*j+1][0], bh[2*j+1][1],
                            bhb + b_off[j] + ko);
#pragma unroll
                for (int i = 0; i < 2; i++)
                    ldsm_x4(ah[i][0], ah[i][1], ah[i][2], ah[i][3],
                            ahb + a_off[i] + ko);
#pragma unroll
                for (int i = 0; i < 2; i++)
#pragma unroll
                    for (int nb = 0; nb < 4; nb++)
                        mma_f16(acc[i][nb], ah[i], bh[nb]);

                uint32_t bl[4][2];
#pragma unroll
                for (int j = 0; j < 2; j++)
                    ldsm_x4(bl[2*j][0], bl[2*j][1], bl[2*j+1][0], bl[2*j+1][1],
                            blb + b_off[j] + ko);
#pragma unroll
                for (int i = 0; i < 2; i++)
#pragma unroll
                    for (int nb = 0; nb < 4; nb++)
                        mma_f16(acc[i][nb], ah[i], bl[nb]);

                uint32_t al[2][4];
#pragma unroll
                for (int i = 0; i < 2; i++)
                    ldsm_x4(al[i][0], al[i][1], al[i][2], al[i][3],
                            alb + a_off[i] + ko);
#pragma unroll
                for (int i = 0; i < 2; i++)
#pragma unroll
                    for (int nb = 0; nb < 4; nb++)
                        mma_f16(acc[i][nb], al[i], bh[nb]);
            }

            // All warps done reading buf; safe to overwrite with stage c+2.
            __syncthreads();
            if (c + 2 < NSTAGE)
                ISSUE_STAGE(c + 2, buf);
        }

        // ---- fused epilogue for this tile ----
        const int t = lane & 3;
        const int grow = lane >> 2;
        const int hb = ((n0 + wn * 32) >> 2) + 2 * t;

        const float tu[2] = {tau[hb], tau[hb + 1]};
        const float sh[2] = {s[hb], s[hb + 1]};
        float bi[4][2];
#pragma unroll
        for (int g = 0; g < 4; g++) {
            bi[g][0] = bias[g * H_DIM + hb];
            bi[g][1] = bias[g * H_DIM + hb + 1];
        }

#pragma unroll
        for (int i = 0; i < 2; i++) {
#pragma unroll
            for (int rsel = 0; rsel < 2; rsel++) {
                const int r = m0 + wm * 32 + i * 16 + grow + rsel * 8;
                const float tt = time_[r];
                const float2 cx2 = *(const float2*)&cx[(size_t)r * H_DIM + hb];
                const float cxa[2] = {cx2.x, cx2.y};
                float hy2[2], cy2[2];
#pragma unroll
                for (int e = 0; e < 2; e++) {
                    const int d = rsel * 2 + e;
                    float gi = acc[i][0][d] + bi[0][e];
                    float gf = acc[i][1][d] + bi[1][e];
                    float gg = acc[i][2][d] + bi[2][e];
                    float go = acc[i][3][d] + bi[3][e];
                    float phi = fmodf(tt - sh[e], tu[e]) / tu[e];
                    float kg;
                    if (phi < 0.5f * rho)      kg = phi * inv_rho;
                    else if (phi < rho)        kg = 2.0f - phi * inv_rho;
                    else                       kg = alpha * phi;
                    float ft = sigf(gf + 1.0f - kg);
                    float it = sigf(gi) * kg;
                    float gt = tanhf(gg) * kg;
                    float ot = sigf(go) * kg;
                    float cyv = ft * cxa[e] + it * gt;
                    cy2[e] = cyv;
                    hy2[e] = ot * tanhf(cyv);
                }
                *(float2*)&out[(size_t)r * H_DIM + hb] =
                    make_float2(hy2[0], hy2[1]);
                *(float2*)&out[(size_t)B_DIM * H_DIM + (size_t)r * H_DIM + hb] =
                    make_float2(cy2[0], cy2[1]);
            }
        }
    }
}

// ---------------- launch ----------------

extern "C" void kernel_launch(void* const* d_in, const int* in_sizes, int n_in,
                              void* d_out, int out_size) {
    const float* input = (const float*)d_in[0];
    const float* time_ = (const float*)d_in[1];
    const float* hx    = (const float*)d_in[2];
    const float* cx    = (const float*)d_in[3];
    const float* Wxh_w = (const float*)d_in[4];
    const float* Wxh_b = (const float*)d_in[5];
    const float* Whh_w = (const float*)d_in[6];
    const float* tau   = (const float*)d_in[7];
    const float* s     = (const float*)d_in[8];
    const float* alpha = (const float*)d_in[9];
    const float* rho   = (const float*)d_in[10];
    float* out = (float*)d_out;

    cudaFuncSetAttribute(gemm_fused_kernel,
                         cudaFuncAttributeMaxDynamicSharedMemorySize, SMEM_BYTES);

    reset_ctr_kernel<<<1, 1>>>();
    prep_kernel<<<6144, 256>>>(input, hx, Wxh_w, Whh_w);

    gemm_fused_kernel<<<GRID_CTAS, 256, SMEM_BYTES>>>(
        time_, cx, tau, s, alpha, rho, Wxh_b, out);
}